// round 11
// baseline (speedup 1.0000x reference)
#include <cuda_runtime.h>

// RNN_64501818851829 — GB300 sm_103a. Round 11.
// Fused recurrence (R9): a(t)=lrelu(W1u·u+M·a(t-1)+c), o(t)=lrelu(OW1u·u+N·a+d),
// out=ow2·o+ob2. This round: fused weights [M;N] live in REGISTERS.
// 1024 warp-blocks x 32 thr, 4 rows (2 f32x2 pairs). Thread (kh=tid>>4,
// jg=tid&15): 5 neurons (j0=5jg), k-half [20kh,20kh+20), both pairs.
// k-halves combined via tiny shared exchange (2 syncwarps/step).
// Weight LDS in the main loop: ZERO.

typedef unsigned long long u64;

static constexpr int Tn = 1024;
static constexpr int NTHR = 32;
static constexpr int NBLK = 1024;          // 4 rows per block

__device__ __forceinline__ u64 fma2(u64 a, u64 b, u64 c) {
    u64 d; asm("fma.rn.f32x2 %0, %1, %2, %3;" : "=l"(d) : "l"(a), "l"(b), "l"(c));
    return d;
}
__device__ __forceinline__ u64 add2(u64 a, u64 b) {
    u64 d; asm("add.rn.f32x2 %0, %1, %2;" : "=l"(d) : "l"(a), "l"(b));
    return d;
}
__device__ __forceinline__ u64 mul2(u64 a, u64 b) {
    u64 d; asm("mul.rn.f32x2 %0, %1, %2;" : "=l"(d) : "l"(a), "l"(b));
    return d;
}
__device__ __forceinline__ u64 pack2(float lo, float hi) {
    u64 d; asm("mov.b64 %0, {%1, %2};" : "=l"(d) : "f"(lo), "f"(hi));
    return d;
}
__device__ __forceinline__ void unpack2(u64 v, float& lo, float& hi) {
    asm("mov.b64 {%0, %1}, %2;" : "=f"(lo), "=f"(hi) : "l"(v));
}
__device__ __forceinline__ u64 dupf(float x) {
    u64 d; asm("mov.b64 %0, {%1, %1};" : "=l"(d) : "f"(x));
    return d;
}
// exact leaky-relu(0.01): max(x, 0.01*x)
__device__ __forceinline__ u64 lrelu2(u64 x, u64 c001) {
    u64 m = mul2(x, c001);
    float2 xf = *(float2*)&x, mf = *(float2*)&m, r;
    r.x = fmaxf(xf.x, mf.x);
    r.y = fmaxf(xf.y, mf.y);
    return *(u64*)&r;
}

__global__ void __launch_bounds__(NTHR, 1) rnn_kernel(
    const float* __restrict__ inputs,
    const float* __restrict__ w1,  const float* __restrict__ b1,
    const float* __restrict__ w2,  const float* __restrict__ b2,
    const float* __restrict__ ow1, const float* __restrict__ ob1,
    const float* __restrict__ ow2, const float* __restrict__ ob2,
    float* __restrict__ outp)
{
    __shared__ __align__(16) float sW2f[40 * 40];     // prologue only
    __shared__ __align__(16) u64 sZ[2][2][42];        // [buf][pair][40 z + u@40]
    __shared__ __align__(16) u64 sX[16][10];          // k-half exchange
    __shared__ __align__(16) u64 sOutP[2][2][8];      // out-dot partials

    const int tid = threadIdx.x;
    const int kh  = tid >> 4;          // k-half
    const int jg  = tid & 15;          // neuron group (5 neurons)
    const bool isH2H = (jg < 8);
    const int j0 = 5 * jg;
    const int k0 = 20 * kh;
    const int baseRow = blockIdx.x * 4;
    const u64 c001 = dupf(0.01f);

    // ---- stage w2 ----
    for (int idx = tid; idx < 1600; idx += NTHR) sW2f[idx] = w2[idx];
    __syncwarp();

    const float* wrow = isH2H ? (w1 + j0 * 41 + 1)
                              : (ow1 + (j0 - 40) * 41 + 1);

    // ---- prologue: per-thread fused weight block wr[5][20] = W1h @ W2 ----
    float wr[5][20];
    float cd[5];
#pragma unroll
    for (int i = 0; i < 5; i++) {
        cd[i] = 0.0f;
#pragma unroll
        for (int q = 0; q < 20; q++) wr[i][q] = 0.0f;
    }
    for (int m = 0; m < 40; m++) {
        float av[5];
#pragma unroll
        for (int i = 0; i < 5; i++) av[i] = wrow[i * 41 + m];
        float bm = b2[m];
#pragma unroll
        for (int i = 0; i < 5; i++) cd[i] += av[i] * bm;
        float w2v[20];
        const float4* wq = (const float4*)(sW2f + m * 40 + k0);
#pragma unroll
        for (int c = 0; c < 5; c++) *(float4*)&w2v[4 * c] = wq[c];
#pragma unroll
        for (int i = 0; i < 5; i++)
#pragma unroll
            for (int q = 0; q < 20; q++) wr[i][q] += av[i] * w2v[q];
    }

    // ---- per-thread constants ----
    u64 bA[5], wu[5], rW[5];
#pragma unroll
    for (int i = 0; i < 5; i++) {
        float pb = isH2H ? b1[j0 + i] : ob1[j0 - 40 + i];
        bA[i] = (kh == 0) ? dupf(cd[i] + pb) : 0ull;
        wu[i] = dupf(isH2H ? w1[(j0 + i) * 41] : ow1[(j0 - 40 + i) * 41]);
        rW[i] = (!isH2H) ? dupf(ow2[j0 - 40 + i]) : 0ull;
    }
    const u64 bo = dupf(ob2[0]);

    // ---- step t = 0 (h = 0: plain biases, u-column only) ----
    if (kh == 0) {
#pragma unroll
        for (int p = 0; p < 2; p++) {
            int ra = baseRow + 2 * p;
            u64 u0 = pack2(inputs[(size_t)ra * Tn], inputs[(size_t)(ra + 1) * Tn]);
            u64 z[5];
#pragma unroll
            for (int i = 0; i < 5; i++) {
                float pb = isH2H ? b1[j0 + i] : ob1[j0 - 40 + i];
                z[i] = lrelu2(fma2(u0, wu[i], dupf(pb)), c001);
            }
            if (isH2H) {
#pragma unroll
                for (int i = 0; i < 5; i++) sZ[0][p][j0 + i] = z[i];
            } else {
                u64 s = mul2(z[0], rW[0]);
                s = fma2(z[1], rW[1], s); s = fma2(z[2], rW[2], s);
                s = fma2(z[3], rW[3], s); s = fma2(z[4], rW[4], s);
                sOutP[0][p][jg - 8] = s;
            }
        }
    } else if (jg < 2) {
        int ra = baseRow + 2 * jg;
        sZ[0][jg][40] = pack2(inputs[(size_t)ra * Tn + 1],
                              inputs[(size_t)(ra + 1) * Tn + 1]);
    }
    __syncwarp();

    // ---- main loop t = 1 .. 1023 ----
    const int rr0 = baseRow + 2 * jg;  // valid for jg<2 duties
    int cur = 0;
    for (int t = 1; t < Tn; t++) {
        u64 uN = 0ull;
        if (kh == 1 && jg < 2) {
            if (t + 1 < Tn)   // next-input LDG at the top, hidden under GEMV
                uN = pack2(inputs[(size_t)rr0 * Tn + t + 1],
                           inputs[(size_t)(rr0 + 1) * Tn + t + 1]);
            // reduce out(t-1)
            const ulonglong2* pp = (const ulonglong2*)&sOutP[cur][jg][0];
            ulonglong2 p0 = pp[0], p1 = pp[1], p2 = pp[2], p3 = pp[3];
            u64 s = add2(add2(add2(p0.x, p0.y), add2(p1.x, p1.y)),
                         add2(add2(p2.x, p2.y), add2(p3.x, p3.y)));
            s = add2(s, bo);
            float lo, hi; unpack2(s, lo, hi);
            outp[(size_t)rr0 * Tn + (t - 1)] = lo;
            outp[(size_t)(rr0 + 1) * Tn + (t - 1)] = hi;
        }

        // ---- GEMV over this thread's k-half, both pairs; weights in regs ----
        const u64* zA = &sZ[cur][0][k0];
        const u64* zB = &sZ[cur][1][k0];
        u64 accA[5], accB[5];
#pragma unroll
        for (int i = 0; i < 5; i++) { accA[i] = bA[i]; accB[i] = bA[i]; }

        ulonglong2 a01 = *(const ulonglong2*)(zA);
        ulonglong2 a23 = *(const ulonglong2*)(zA + 2);
        ulonglong2 b01 = *(const ulonglong2*)(zB);
        ulonglong2 b23 = *(const ulonglong2*)(zB + 2);
#pragma unroll
        for (int kq = 0; kq < 5; kq++) {
            ulonglong2 na01, na23, nb01, nb23;
            if (kq < 4) {
                na01 = *(const ulonglong2*)(zA + 4 * (kq + 1));
                na23 = *(const ulonglong2*)(zA + 4 * (kq + 1) + 2);
                nb01 = *(const ulonglong2*)(zB + 4 * (kq + 1));
                nb23 = *(const ulonglong2*)(zB + 4 * (kq + 1) + 2);
            }
#pragma unroll
            for (int i = 0; i < 5; i++) {
                u64 w;
                w = dupf(wr[i][4 * kq + 0]);
                accA[i] = fma2(a01.x, w, accA[i]); accB[i] = fma2(b01.x, w, accB[i]);
                w = dupf(wr[i][4 * kq + 1]);
                accA[i] = fma2(a01.y, w, accA[i]); accB[i] = fma2(b01.y, w, accB[i]);
                w = dupf(wr[i][4 * kq + 2]);
                accA[i] = fma2(a23.x, w, accA[i]); accB[i] = fma2(b23.x, w, accB[i]);
                w = dupf(wr[i][4 * kq + 3]);
                accA[i] = fma2(a23.y, w, accA[i]); accB[i] = fma2(b23.y, w, accB[i]);
            }
            if (kq < 4) { a01 = na01; a23 = na23; b01 = nb01; b23 = nb23; }
        }

        if (kh == 1) {     // u-term + store k-half partials
            u64 ua = sZ[cur][0][40], ub = sZ[cur][1][40];
#pragma unroll
            for (int i = 0; i < 5; i++) {
                accA[i] = fma2(ua, wu[i], accA[i]);
                accB[i] = fma2(ub, wu[i], accB[i]);
            }
            ulonglong2* d = (ulonglong2*)&sX[jg][0];
            d[0] = make_ulonglong2(accA[0], accA[1]);
            d[1] = make_ulonglong2(accA[2], accA[3]);
            d[2] = make_ulonglong2(accA[4], accB[0]);
            d[3] = make_ulonglong2(accB[1], accB[2]);
            d[4] = make_ulonglong2(accB[3], accB[4]);
        }
        __syncwarp();

        const int nxt = cur ^ 1;
        if (kh == 0) {     // combine halves, lrelu, distribute
            const ulonglong2* q = (const ulonglong2*)&sX[jg][0];
            ulonglong2 q0 = q[0], q1 = q[1], q2 = q[2], q3 = q[3], q4 = q[4];
            u64 zA0 = lrelu2(add2(accA[0], q0.x), c001);
            u64 zA1 = lrelu2(add2(accA[1], q0.y), c001);
            u64 zA2 = lrelu2(add2(accA[2], q1.x), c001);
            u64 zA3 = lrelu2(add2(accA[3], q1.y), c001);
            u64 zA4 = lrelu2(add2(accA[4], q2.x), c001);
            u64 zB0 = lrelu2(add2(accB[0], q2.y), c001);
            u64 zB1 = lrelu2(add2(accB[1], q3.x), c001);
            u64 zB2 = lrelu2(add2(accB[2], q3.y), c001);
            u64 zB3 = lrelu2(add2(accB[3], q4.x), c001);
            u64 zB4 = lrelu2(add2(accB[4], q4.y), c001);
            if (isH2H) {   // a(t) -> next buffer
                sZ[nxt][0][j0 + 0] = zA0; sZ[nxt][0][j0 + 1] = zA1;
                sZ[nxt][0][j0 + 2] = zA2; sZ[nxt][0][j0 + 3] = zA3;
                sZ[nxt][0][j0 + 4] = zA4;
                sZ[nxt][1][j0 + 0] = zB0; sZ[nxt][1][j0 + 1] = zB1;
                sZ[nxt][1][j0 + 2] = zB2; sZ[nxt][1][j0 + 3] = zB3;
                sZ[nxt][1][j0 + 4] = zB4;
            } else {       // o(t) -> out-dot partials
                u64 s = mul2(zA0, rW[0]);
                s = fma2(zA1, rW[1], s); s = fma2(zA2, rW[2], s);
                s = fma2(zA3, rW[3], s); s = fma2(zA4, rW[4], s);
                sOutP[nxt][0][jg - 8] = s;
                u64 r = mul2(zB0, rW[0]);
                r = fma2(zB1, rW[1], r); r = fma2(zB2, rW[2], r);
                r = fma2(zB3, rW[3], r); r = fma2(zB4, rW[4], r);
                sOutP[nxt][1][jg - 8] = r;
            }
        }
        if (kh == 1 && jg < 2) sZ[nxt][jg][40] = uN;
        __syncwarp();
        cur = nxt;
    }

    // final out(1023)
    if (kh == 1 && jg < 2) {
        const ulonglong2* pp = (const ulonglong2*)&sOutP[cur][jg][0];
        ulonglong2 p0 = pp[0], p1 = pp[1], p2 = pp[2], p3 = pp[3];
        u64 s = add2(add2(add2(p0.x, p0.y), add2(p1.x, p1.y)),
                     add2(add2(p2.x, p2.y), add2(p3.x, p3.y)));
        s = add2(s, bo);
        float lo, hi; unpack2(s, lo, hi);
        outp[(size_t)rr0 * Tn + (Tn - 1)] = lo;
        outp[(size_t)(rr0 + 1) * Tn + (Tn - 1)] = hi;
    }
}

extern "C" void kernel_launch(void* const* d_in, const int* in_sizes, int n_in,
                              void* d_out, int out_size) {
    const float* inputs = (const float*)d_in[0];
    const float* w1  = (const float*)d_in[1];
    const float* b1  = (const float*)d_in[2];
    const float* w2  = (const float*)d_in[3];
    const float* b2  = (const float*)d_in[4];
    const float* ow1 = (const float*)d_in[5];
    const float* ob1 = (const float*)d_in[6];
    const float* ow2 = (const float*)d_in[7];
    const float* ob2 = (const float*)d_in[8];
    float* out = (float*)d_out;

    rnn_kernel<<<NBLK, NTHR>>>(inputs, w1, b1, w2, b2,
                               ow1, ob1, ow2, ob2, out);
}

// round 12
// speedup vs baseline: 1.4011x; 1.4011x over previous
#include <cuda_runtime.h>

// RNN_64501818851829 — GB300 sm_103a. Round 12.
// Fused recurrence (R9): a(t)=lrelu(W1u·u+M·a(t-1)+c), o(t)=lrelu(OW1u·u+N·a+d),
// out=ow2·o+ob2, M=W1h·W2, N=OW1h·W2.
// NEW: neuron-split across two warps. 512 blocks x 64 threads, 8 rows/block.
//   warp0 = neurons 0..39 (M, produces a(t)); warp1 = neurons 40..79 (N,
//   produces out partials). Thread (jg=lid>>2, pair=lid&3): 5 neurons x
//   full k=40 x 1 pair. Per-warp weight traffic halves vs R10; coalesced
//   weight layout [kq][i][jg] -> 1 wavefront per weight LDS.128.
// One __syncthreads per step; out-reduction and input LDG pipelined.

typedef unsigned long long u64;

static constexpr int Tn = 1024;
static constexpr int NTHR = 64;
static constexpr int NBLK = 512;           // 8 rows per block

__device__ __forceinline__ u64 fma2(u64 a, u64 b, u64 c) {
    u64 d; asm("fma.rn.f32x2 %0, %1, %2, %3;" : "=l"(d) : "l"(a), "l"(b), "l"(c));
    return d;
}
__device__ __forceinline__ u64 add2(u64 a, u64 b) {
    u64 d; asm("add.rn.f32x2 %0, %1, %2;" : "=l"(d) : "l"(a), "l"(b));
    return d;
}
__device__ __forceinline__ u64 mul2(u64 a, u64 b) {
    u64 d; asm("mul.rn.f32x2 %0, %1, %2;" : "=l"(d) : "l"(a), "l"(b));
    return d;
}
__device__ __forceinline__ u64 pack2(float lo, float hi) {
    u64 d; asm("mov.b64 %0, {%1, %2};" : "=l"(d) : "f"(lo), "f"(hi));
    return d;
}
__device__ __forceinline__ void unpack2(u64 v, float& lo, float& hi) {
    asm("mov.b64 {%0, %1}, %2;" : "=f"(lo), "=f"(hi) : "l"(v));
}
__device__ __forceinline__ u64 dupf(float x) {
    u64 d; asm("mov.b64 %0, {%1, %1};" : "=l"(d) : "f"(x));
    return d;
}
// exact leaky-relu(0.01): max(x, 0.01*x)
__device__ __forceinline__ u64 lrelu2(u64 x, u64 c001) {
    u64 m = mul2(x, c001);
    float2 xf = *(float2*)&x, mf = *(float2*)&m, r;
    r.x = fmaxf(xf.x, mf.x);
    r.y = fmaxf(xf.y, mf.y);
    return *(u64*)&r;
}

__global__ void __launch_bounds__(NTHR, 1) rnn_kernel(
    const float* __restrict__ inputs,
    const float* __restrict__ w1,  const float* __restrict__ b1,
    const float* __restrict__ w2,  const float* __restrict__ b2,
    const float* __restrict__ ow1, const float* __restrict__ ob1,
    const float* __restrict__ ow2, const float* __restrict__ ob2,
    float* __restrict__ outp)
{
    // fused weights: float4 index = kq*80 + wid*40 + i*8 + jg  (i=0..4, jg=0..7)
    __shared__ __align__(16) float fWA[10 * 80 * 4];   // 12800 B
    __shared__ __align__(16) float sW2f[40 * 40];      //  6400 B (prologue)
    __shared__ __align__(16) u64 sZ[2][4][42];         // [buf][pair][40 z, u@40]
    __shared__ __align__(16) u64 sOutP[2][4][8];       // [buf][pair][jg]

    const int tid  = threadIdx.x;
    const int wid  = tid >> 5;         // 0: h2h (M), 1: h2o (N)
    const int lid  = tid & 31;
    const int jg   = lid >> 2;         // 0..7
    const int pair = lid & 3;          // 0..3
    const int j0   = 5 * jg;           // local neuron base within half
    const int baseRow = blockIdx.x * 8;
    const u64 c001 = dupf(0.01f);

    // ---- stage w2 ----
    for (int idx = tid; idx < 1600; idx += NTHR) sW2f[idx] = w2[idx];
    __syncthreads();

    // this thread's 5 rows of its half's L1 hidden block (stride 41, col 1..40)
    const float* wrow = (wid == 0) ? (w1 + j0 * 41 + 1)
                                   : (ow1 + j0 * 41 + 1);

    // ---- prologue: fused [M;N] = W1h @ W2 -> fWA (pair==0 lanes compute) ----
    if (pair == 0) {
        for (int pass = 0; pass < 4; pass++) {
            const int k0 = 10 * pass;
            float acc[5][10];
#pragma unroll
            for (int i = 0; i < 5; i++)
#pragma unroll
                for (int q = 0; q < 10; q++) acc[i][q] = 0.0f;
            for (int m = 0; m < 40; m++) {
                float av[5];
#pragma unroll
                for (int i = 0; i < 5; i++) av[i] = wrow[i * 41 + m];
                float wv[10];
#pragma unroll
                for (int q = 0; q < 10; q++) wv[q] = sW2f[m * 40 + k0 + q];
#pragma unroll
                for (int i = 0; i < 5; i++)
#pragma unroll
                    for (int q = 0; q < 10; q++) acc[i][q] += av[i] * wv[q];
            }
#pragma unroll
            for (int i = 0; i < 5; i++)
#pragma unroll
                for (int q = 0; q < 10; q++) {
                    int k = k0 + q;
                    fWA[((k >> 2) * 80 + wid * 40 + i * 8 + jg) * 4 + (k & 3)] =
                        acc[i][q];
                }
        }
    }

    // ---- per-thread constants: fused bias, u-weights, out-dot weights ----
    u64 bA[5], wu[5], rW[5];
    {
        float cd[5] = {0, 0, 0, 0, 0};
        for (int m = 0; m < 40; m++) {
            float bv = b2[m];
#pragma unroll
            for (int i = 0; i < 5; i++) cd[i] += wrow[i * 41 + m] * bv;
        }
#pragma unroll
        for (int i = 0; i < 5; i++) {
            float pb = (wid == 0) ? b1[j0 + i] : ob1[j0 + i];
            bA[i] = dupf(cd[i] + pb);
            wu[i] = dupf((wid == 0) ? w1[(j0 + i) * 41] : ow1[(j0 + i) * 41]);
            rW[i] = (wid == 1) ? dupf(ow2[j0 + i]) : 0ull;
        }
    }
    const u64 bo = dupf(ob2[0]);
    const int r0 = baseRow + 2 * pair, r1 = r0 + 1;
    __syncthreads();   // fWA ready

    // ---- step t = 0 (h = 0: plain biases, u-column only) ----
    {
        u64 u0 = pack2(inputs[(size_t)r0 * Tn], inputs[(size_t)r1 * Tn]);
        u64 z[5];
#pragma unroll
        for (int i = 0; i < 5; i++) {
            float pb = (wid == 0) ? b1[j0 + i] : ob1[j0 + i];
            z[i] = lrelu2(fma2(u0, wu[i], dupf(pb)), c001);
        }
        if (wid == 0) {
#pragma unroll
            for (int i = 0; i < 5; i++) sZ[0][pair][j0 + i] = z[i];
        } else {
            u64 s = mul2(z[0], rW[0]);
            s = fma2(z[1], rW[1], s); s = fma2(z[2], rW[2], s);
            s = fma2(z[3], rW[3], s); s = fma2(z[4], rW[4], s);
            sOutP[0][pair][jg] = s;
        }
        if (wid == 0 && lid < 4) {  // u(1) into buffer 0 (pair = lid)
            int ra = baseRow + 2 * lid;
            sZ[0][lid][40] = pack2(inputs[(size_t)ra * Tn + 1],
                                   inputs[(size_t)(ra + 1) * Tn + 1]);
        }
    }
    __syncthreads();

    // ---- main loop t = 1 .. 1023 (one __syncthreads per step) ----
    const float4* wA4 = (const float4*)fWA + wid * 40 + jg;
    int cur = 0;
    for (int t = 1; t < Tn; t++) {
        u64 uN = 0ull;
        if (wid == 0 && lid < 4 && t + 1 < Tn) {  // next-input LDG, hidden
            int ra = baseRow + 2 * lid;
            uN = pack2(inputs[(size_t)ra * Tn + t + 1],
                       inputs[(size_t)(ra + 1) * Tn + t + 1]);
        }
        if (wid == 1 && lid < 4) {  // reduce out(t-1) for pair = lid
            const ulonglong2* pp = (const ulonglong2*)&sOutP[cur][lid][0];
            ulonglong2 p0 = pp[0], p1 = pp[1], p2 = pp[2], p3 = pp[3];
            u64 s = add2(add2(add2(p0.x, p0.y), add2(p1.x, p1.y)),
                         add2(add2(p2.x, p2.y), add2(p3.x, p3.y)));
            s = add2(s, bo);
            float lo, hi; unpack2(s, lo, hi);
            int ra = baseRow + 2 * lid;
            outp[(size_t)ra * Tn + (t - 1)] = lo;
            outp[(size_t)(ra + 1) * Tn + (t - 1)] = hi;
        }

        // ---- GEMV: 5 neurons x full k=40 x 1 pair, pipelined over kq ----
        const u64* zb = &sZ[cur][pair][0];
        u64 a0 = bA[0], a1 = bA[1], a2 = bA[2], a3 = bA[3], a4 = bA[4];

        ulonglong2 z01 = *(const ulonglong2*)(zb);
        ulonglong2 z23 = *(const ulonglong2*)(zb + 2);
        float4 v0 = wA4[0], v1 = wA4[8], v2 = wA4[16], v3 = wA4[24], v4 = wA4[32];

#pragma unroll
        for (int kq = 0; kq < 10; kq++) {
            ulonglong2 nz01, nz23;
            float4 n0, n1, n2, n3, n4;
            if (kq < 9) {
                nz01 = *(const ulonglong2*)(zb + 4 * (kq + 1));
                nz23 = *(const ulonglong2*)(zb + 4 * (kq + 1) + 2);
                n0 = wA4[(kq + 1) * 80 + 0];
                n1 = wA4[(kq + 1) * 80 + 8];
                n2 = wA4[(kq + 1) * 80 + 16];
                n3 = wA4[(kq + 1) * 80 + 24];
                n4 = wA4[(kq + 1) * 80 + 32];
            }
            u64 dx;
            dx = dupf(v0.x); a0 = fma2(z01.x, dx, a0);
            dx = dupf(v0.y); a0 = fma2(z01.y, dx, a0);
            dx = dupf(v0.z); a0 = fma2(z23.x, dx, a0);
            dx = dupf(v0.w); a0 = fma2(z23.y, dx, a0);
            dx = dupf(v1.x); a1 = fma2(z01.x, dx, a1);
            dx = dupf(v1.y); a1 = fma2(z01.y, dx, a1);
            dx = dupf(v1.z); a1 = fma2(z23.x, dx, a1);
            dx = dupf(v1.w); a1 = fma2(z23.y, dx, a1);
            dx = dupf(v2.x); a2 = fma2(z01.x, dx, a2);
            dx = dupf(v2.y); a2 = fma2(z01.y, dx, a2);
            dx = dupf(v2.z); a2 = fma2(z23.x, dx, a2);
            dx = dupf(v2.w); a2 = fma2(z23.y, dx, a2);
            dx = dupf(v3.x); a3 = fma2(z01.x, dx, a3);
            dx = dupf(v3.y); a3 = fma2(z01.y, dx, a3);
            dx = dupf(v3.z); a3 = fma2(z23.x, dx, a3);
            dx = dupf(v3.w); a3 = fma2(z23.y, dx, a3);
            dx = dupf(v4.x); a4 = fma2(z01.x, dx, a4);
            dx = dupf(v4.y); a4 = fma2(z01.y, dx, a4);
            dx = dupf(v4.z); a4 = fma2(z23.x, dx, a4);
            dx = dupf(v4.w); a4 = fma2(z23.y, dx, a4);
            if (kq < 9) {
                z01 = nz01; z23 = nz23;
                v0 = n0; v1 = n1; v2 = n2; v3 = n3; v4 = n4;
            }
        }
        {   // u-term (weights in registers)
            u64 ua = zb[40];
            a0 = fma2(ua, wu[0], a0);
            a1 = fma2(ua, wu[1], a1);
            a2 = fma2(ua, wu[2], a2);
            a3 = fma2(ua, wu[3], a3);
            a4 = fma2(ua, wu[4], a4);
        }
        a0 = lrelu2(a0, c001);
        a1 = lrelu2(a1, c001);
        a2 = lrelu2(a2, c001);
        a3 = lrelu2(a3, c001);
        a4 = lrelu2(a4, c001);

        const int nxt = cur ^ 1;
        if (wid == 0) {   // a(t) -> next buffer
            u64* d = &sZ[nxt][pair][j0];
            d[0] = a0; d[1] = a1; d[2] = a2; d[3] = a3; d[4] = a4;
        } else {          // o(t) -> out-dot partials (reduced next step)
            u64 s = mul2(a0, rW[0]);
            s = fma2(a1, rW[1], s); s = fma2(a2, rW[2], s);
            s = fma2(a3, rW[3], s); s = fma2(a4, rW[4], s);
            sOutP[nxt][pair][jg] = s;
        }
        if (wid == 0 && lid < 4)   // u(t+1) into next buffer
            sZ[nxt][lid][40] = uN;
        __syncthreads();
        cur = nxt;
    }

    // final out(1023)
    if (wid == 1 && lid < 4) {
        const ulonglong2* pp = (const ulonglong2*)&sOutP[cur][lid][0];
        ulonglong2 p0 = pp[0], p1 = pp[1], p2 = pp[2], p3 = pp[3];
        u64 s = add2(add2(add2(p0.x, p0.y), add2(p1.x, p1.y)),
                     add2(add2(p2.x, p2.y), add2(p3.x, p3.y)));
        s = add2(s, bo);
        float lo, hi; unpack2(s, lo, hi);
        int ra = baseRow + 2 * lid;
        outp[(size_t)ra * Tn + (Tn - 1)] = lo;
        outp[(size_t)(ra + 1) * Tn + (Tn - 1)] = hi;
    }
}

extern "C" void kernel_launch(void* const* d_in, const int* in_sizes, int n_in,
                              void* d_out, int out_size) {
    const float* inputs = (const float*)d_in[0];
    const float* w1  = (const float*)d_in[1];
    const float* b1  = (const float*)d_in[2];
    const float* w2  = (const float*)d_in[3];
    const float* b2  = (const float*)d_in[4];
    const float* ow1 = (const float*)d_in[5];
    const float* ob1 = (const float*)d_in[6];
    const float* ow2 = (const float*)d_in[7];
    const float* ob2 = (const float*)d_in[8];
    float* out = (float*)d_out;

    rnn_kernel<<<NBLK, NTHR>>>(inputs, w1, b1, w2, b2,
                               ow1, ob1, ow2, ob2, out);
}